// round 8
// baseline (speedup 1.0000x reference)
#include <cuda_runtime.h>
#include <cuda_bf16.h>
#include <cstdint>

// ============================================================================
// Fully-fused tensor-core GRU, software-pipelined, dual gh chains.
// B=2048, T=256, F=128, H=64. 128 blocks x 256 threads, 16 rows/block.
// ============================================================================

#define Bn 2048
#define Tn 256
#define Fn 128
#define Hn 64
#define ROWS 16
#define NTH 256

// smem offsets (bytes)
#define WIH_H 0                 // 192 x 272
#define WIH_L 52224
#define WHH_H 104448            // 192 x 144
#define WHH_L 132096
#define XB    159744            // x bf16: hi bufs [2], then lo bufs [2], 4352 each
#define XSZ   4352
#define XLO   8704
#define HBB   177152            // h bf16: hi bufs [2], then lo bufs [2], 2304 each
#define HSZ   2304
#define HLO   4608
#define HF    186368            // fp32 h_last: 16 x 68
#define SMEMB 190720

__device__ __forceinline__ uint32_t smem_u32(const void* p) {
    uint32_t a;
    asm("{ .reg .u64 t; cvta.to.shared.u64 t, %1; cvt.u32.u64 %0, t; }"
        : "=r"(a) : "l"(p));
    return a;
}
__device__ __forceinline__ void ldsm4(uint32_t* r, uint32_t addr) {
    asm volatile("ldmatrix.sync.aligned.m8n8.x4.shared.b16 {%0,%1,%2,%3}, [%4];"
        : "=r"(r[0]), "=r"(r[1]), "=r"(r[2]), "=r"(r[3]) : "r"(addr));
}
__device__ __forceinline__ void ldsm2(uint32_t* r, uint32_t addr) {
    asm volatile("ldmatrix.sync.aligned.m8n8.x2.shared.b16 {%0,%1}, [%2];"
        : "=r"(r[0]), "=r"(r[1]) : "r"(addr));
}
__device__ __forceinline__ void mma16816(float* c, const uint32_t* a,
                                         uint32_t b0, uint32_t b1) {
    asm volatile(
        "mma.sync.aligned.m16n8k16.row.col.f32.bf16.bf16.f32 "
        "{%0,%1,%2,%3}, {%4,%5,%6,%7}, {%8,%9}, {%0,%1,%2,%3};"
        : "+f"(c[0]), "+f"(c[1]), "+f"(c[2]), "+f"(c[3])
        : "r"(a[0]), "r"(a[1]), "r"(a[2]), "r"(a[3]), "r"(b0), "r"(b1));
}
__device__ __forceinline__ void split_store(char* sm, int off_hi, int off_lo,
                                            int boff, float4 v) {
    __nv_bfloat162 h01 = __floats2bfloat162_rn(v.x, v.y);
    __nv_bfloat162 h23 = __floats2bfloat162_rn(v.z, v.w);
    *(uint2*)(sm + off_hi + boff) = make_uint2(*(uint32_t*)&h01, *(uint32_t*)&h23);
    float l0 = v.x - __bfloat162float(__low2bfloat16(h01));
    float l1 = v.y - __bfloat162float(__high2bfloat16(h01));
    float l2 = v.z - __bfloat162float(__low2bfloat16(h23));
    float l3 = v.w - __bfloat162float(__high2bfloat16(h23));
    __nv_bfloat162 s01 = __floats2bfloat162_rn(l0, l1);
    __nv_bfloat162 s23 = __floats2bfloat162_rn(l2, l3);
    *(uint2*)(sm + off_lo + boff) = make_uint2(*(uint32_t*)&s01, *(uint32_t*)&s23);
}
__device__ __forceinline__ float tanh_ap(float v) {
    float r;
    asm("tanh.approx.f32 %0, %1;" : "=f"(r) : "f"(v));
    return r;
}
__device__ __forceinline__ float sig_t(float v) {
    return fmaf(0.5f, tanh_ap(0.5f * v), 0.5f);
}

// one GRU time step; CUR = buffer parity of h(t)/x(t); gxc = gx(t) (consumed),
// gxn = gx(t+1) (produced). Everything inlined, all indices constant.
template<int CUR>
__device__ __forceinline__ void gru_step(
    int t, char* sm, uint32_t sb,
    const float4* x4, size_t xrow, int pc, int pr,
    uint32_t aX, uint32_t aH, int u0, int r_l,
    const uint32_t wihH[3][8][2], const uint32_t wihL[3][8][2],
    const uint32_t whhH[3][4][2], const uint32_t* whhLa,
    const float* brz_r, const float* brz_z,
    const float* bn_x, const float* bn_h,
    float* hold, float (*gxc)[4], float (*gxn)[4])
{
    constexpr int NXT = CUR ^ 1;

    // x(t+2) gmem prefetch
    float4 p0, p1;
    const bool pf2 = (t + 2 < Tn);
    if (pf2) {
        p0 = x4[xrow + (size_t)(t + 2) * 32 + pc];
        p1 = x4[xrow + (size_t)(t + 2) * 32 + pc + 1];
    }

    // dual gh chains; biases folded
    float ghR[2][4], ghZ[2][4], ghN[2][4];
    #pragma unroll
    for (int i = 0; i < 4; ++i) {
        ghR[0][i] = 0.f; ghZ[0][i] = 0.f; ghN[0][i] = bn_h[i & 1];
        ghR[1][i] = 0.f; ghZ[1][i] = 0.f; ghN[1][i] = 0.f;
        gxn[0][i] = brz_r[i & 1]; gxn[1][i] = brz_z[i & 1]; gxn[2][i] = bn_x[i & 1];
    }

    const uint32_t xh = sb + XB + NXT * XSZ + aX;   // x(t+1)
    const uint32_t xl = xh + XLO;
    const uint32_t hh = sb + HBB + CUR * HSZ + aH;  // h(t)
    const uint32_t hl = hh + HLO;

    #pragma unroll
    for (int q = 0; q < 4; ++q) {
        uint32_t hah[4], hal[4], wl0[2], wl1[2], wl2[2];
        ldsm4(hah, hh + q * 32);
        ldsm4(hal, hl + q * 32);
        ldsm2(wl0, whhLa[0] + q * 32);
        ldsm2(wl1, whhLa[1] + q * 32);
        ldsm2(wl2, whhLa[2] + q * 32);

        // gx filler: ksteps 2q, 2q+1 for q<3 (ks 6,7 reserved for the tail)
        if (q < 3) {
            #pragma unroll
            for (int s = 0; s < 2; ++s) {
                const int ks = 2 * q + s;
                uint32_t ah[4], al[4];
                ldsm4(ah, xh + ks * 32);
                ldsm4(al, xl + ks * 32);
                mma16816(gxn[0], ah, wihH[0][ks][0], wihH[0][ks][1]);
                mma16816(gxn[1], ah, wihH[1][ks][0], wihH[1][ks][1]);
                mma16816(gxn[2], ah, wihH[2][ks][0], wihH[2][ks][1]);
                mma16816(gxn[0], ah, wihL[0][ks][0], wihL[0][ks][1]);
                mma16816(gxn[1], ah, wihL[1][ks][0], wihL[1][ks][1]);
                mma16816(gxn[2], ah, wihL[2][ks][0], wihL[2][ks][1]);
                mma16816(gxn[0], al, wihH[0][ks][0], wihH[0][ks][1]);
                mma16816(gxn[1], al, wihH[1][ks][0], wihH[1][ks][1]);
                mma16816(gxn[2], al, wihH[2][ks][0], wihH[2][ks][1]);
            }
        }

        const int cc = q >> 1;
        mma16816(ghR[cc], hah, whhH[0][q][0], whhH[0][q][1]);
        mma16816(ghZ[cc], hah, whhH[1][q][0], whhH[1][q][1]);
        mma16816(ghN[cc], hah, whhH[2][q][0], whhH[2][q][1]);
        mma16816(ghR[cc], hah, wl0[0], wl0[1]);
        mma16816(ghZ[cc], hah, wl1[0], wl1[1]);
        mma16816(ghN[cc], hah, wl2[0], wl2[1]);
        mma16816(ghR[cc], hal, whhH[0][q][0], whhH[0][q][1]);
        mma16816(ghZ[cc], hal, whhH[1][q][0], whhH[1][q][1]);
        mma16816(ghN[cc], hal, whhH[2][q][0], whhH[2][q][1]);
    }

    // gx tail ksteps 6,7 — independent tensor work covering the gh chain tail
    #pragma unroll
    for (int ks = 6; ks < 8; ++ks) {
        uint32_t ah[4], al[4];
        ldsm4(ah, xh + ks * 32);
        ldsm4(al, xl + ks * 32);
        mma16816(gxn[0], ah, wihH[0][ks][0], wihH[0][ks][1]);
        mma16816(gxn[1], ah, wihH[1][ks][0], wihH[1][ks][1]);
        mma16816(gxn[2], ah, wihH[2][ks][0], wihH[2][ks][1]);
        mma16816(gxn[0], ah, wihL[0][ks][0], wihL[0][ks][1]);
        mma16816(gxn[1], ah, wihL[1][ks][0], wihL[1][ks][1]);
        mma16816(gxn[2], ah, wihL[2][ks][0], wihL[2][ks][1]);
        mma16816(gxn[0], al, wihH[0][ks][0], wihH[0][ks][1]);
        mma16816(gxn[1], al, wihH[1][ks][0], wihH[1][ks][1]);
        mma16816(gxn[2], al, wihH[2][ks][0], wihH[2][ks][1]);
    }

    // gates + h update
    #pragma unroll
    for (int idx = 0; idx < 4; ++idx) {
        float rr = sig_t(ghR[0][idx] + ghR[1][idx] + gxc[0][idx]);
        float zz = sig_t(ghZ[0][idx] + ghZ[1][idx] + gxc[1][idx]);
        float nn = tanh_ap(gxc[2][idx] + rr * (ghN[0][idx] + ghN[1][idx]));
        hold[idx] = (1.0f - zz) * nn + zz * hold[idx];
    }

    // x(t+2) into buffer parity CUR (x(t) is dead)
    if (pf2) {
        split_store(sm, XB + CUR * XSZ, XB + XLO + CUR * XSZ,
                    pr * 272 + pc * 8, p0);
        split_store(sm, XB + CUR * XSZ, XB + XLO + CUR * XSZ,
                    pr * 272 + (pc + 1) * 8, p1);
    }

    // h(t+1) bf16 hi/lo into NXT buffer
    #pragma unroll
    for (int i = 0; i < 2; ++i) {
        int row = r_l + 8 * i;
        float a0 = hold[2 * i], a1 = hold[2 * i + 1];
        __nv_bfloat162 hb2 = __floats2bfloat162_rn(a0, a1);
        *(uint32_t*)(sm + HBB + NXT * HSZ + row * 144 + u0 * 2) =
            *(uint32_t*)&hb2;
        float e0 = a0 - __bfloat162float(__low2bfloat16(hb2));
        float e1 = a1 - __bfloat162float(__high2bfloat16(hb2));
        __nv_bfloat162 lb2 = __floats2bfloat162_rn(e0, e1);
        *(uint32_t*)(sm + HBB + HLO + NXT * HSZ + row * 144 + u0 * 2) =
            *(uint32_t*)&lb2;
    }

    __syncthreads();
}

__global__ void __launch_bounds__(NTH, 1)
gru_fused_tc(const float* __restrict__ x,
             const float* __restrict__ w_ih,
             const float* __restrict__ w_hh,
             const float* __restrict__ b_ih,
             const float* __restrict__ b_hh,
             const float* __restrict__ fc_w,
             const float* __restrict__ fc_b,
             float* __restrict__ out) {
    extern __shared__ char sm[];
    const uint32_t sb = smem_u32(sm);
    const int tid = threadIdx.x;
    const int w   = tid >> 5;
    const int l   = tid & 31;
    const int r0  = blockIdx.x * ROWS;

    const int u0 = 8 * w + 2 * (l & 3);
    float brz_r[2], brz_z[2], bn_x[2], bn_h[2];
    #pragma unroll
    for (int j = 0; j < 2; ++j) {
        brz_r[j] = b_ih[u0 + j]      + b_hh[u0 + j];
        brz_z[j] = b_ih[64 + u0 + j] + b_hh[64 + u0 + j];
        bn_x[j]  = b_ih[128 + u0 + j];
        bn_h[j]  = b_hh[128 + u0 + j];
    }

    // weights -> smem hi/lo
    {
        const float4* w4 = (const float4*)w_ih;
        #pragma unroll
        for (int j = 0; j < 24; ++j) {
            int idx = j * 256 + tid;
            int row = idx >> 5, c4 = idx & 31;
            split_store(sm, WIH_H, WIH_L, row * 272 + c4 * 8, w4[idx]);
        }
        const float4* v4 = (const float4*)w_hh;
        #pragma unroll
        for (int j = 0; j < 12; ++j) {
            int idx = j * 256 + tid;
            int row = idx >> 4, c4 = idx & 15;
            split_store(sm, WHH_H, WHH_L, row * 144 + c4 * 8, v4[idx]);
        }
        for (int i = tid; i < (4 * HSZ) / 4; i += NTH)
            *(uint32_t*)(sm + HBB + i * 4) = 0u;
    }
    __syncthreads();

    // resident B fragments: wih hi/lo, whh hi. whh lo re-loaded per step.
    const int lq = l & 15;
    uint32_t wihH[3][8][2], wihL[3][8][2], whhH[3][4][2];
    uint32_t whhLa[3];
    #pragma unroll
    for (int g = 0; g < 3; ++g) {
        const uint32_t rbase = (uint32_t)(g * 64 + 8 * w + (lq & 7));
        #pragma unroll
        for (int ks = 0; ks < 8; ++ks) {
            uint32_t off = rbase * 272 + ks * 32 + (lq >> 3) * 16;
            ldsm2(wihH[g][ks], sb + WIH_H + off);
            ldsm2(wihL[g][ks], sb + WIH_L + off);
        }
        #pragma unroll
        for (int ks = 0; ks < 4; ++ks) {
            uint32_t off = rbase * 144 + ks * 32 + (lq >> 3) * 16;
            ldsm2(whhH[g][ks], sb + WHH_H + off);
        }
        whhLa[g] = sb + WHH_L + rbase * 144 + (lq >> 3) * 16;
    }

    const int mrow  = (l & 7) + ((l >> 3) & 1) * 8;
    const int khalf = (l >> 4) & 1;
    const uint32_t aX = (uint32_t)(mrow * 272 + khalf * 16);
    const uint32_t aH = (uint32_t)(mrow * 144 + khalf * 16);

    const int pr = tid >> 4;
    const int pc = (tid & 15) * 2;
    const float4* x4 = (const float4*)x;
    const size_t xrow = (size_t)(r0 + pr) * (Tn * Fn / 4);

    // preload x(0)->buf0, x(1)->buf1
    {
        float4 v0 = x4[xrow + pc];
        float4 v1 = x4[xrow + pc + 1];
        split_store(sm, XB, XB + XLO, pr * 272 + pc * 8, v0);
        split_store(sm, XB, XB + XLO, pr * 272 + (pc + 1) * 8, v1);
        v0 = x4[xrow + 32 + pc];
        v1 = x4[xrow + 32 + pc + 1];
        split_store(sm, XB + XSZ, XB + XLO + XSZ, pr * 272 + pc * 8, v0);
        split_store(sm, XB + XSZ, XB + XLO + XSZ, pr * 272 + (pc + 1) * 8, v1);
    }
    __syncthreads();

    const int r_l = l >> 2;
    float hold[4] = {0.f, 0.f, 0.f, 0.f};

    // prologue: gx(0) from buf0
    float gxa[3][4], gxb[3][4];
    #pragma unroll
    for (int i = 0; i < 4; ++i) {
        gxa[0][i] = brz_r[i & 1]; gxa[1][i] = brz_z[i & 1]; gxa[2][i] = bn_x[i & 1];
    }
    {
        const uint32_t xh = sb + XB + aX;
        const uint32_t xl = xh + XLO;
        #pragma unroll
        for (int ks = 0; ks < 8; ++ks) {
            uint32_t ah[4], al[4];
            ldsm4(ah, xh + ks * 32);
            ldsm4(al, xl + ks * 32);
            mma16816(gxa[0], ah, wihH[0][ks][0], wihH[0][ks][1]);
            mma16816(gxa[1], ah, wihH[1][ks][0], wihH[1][ks][1]);
            mma16816(gxa[2], ah, wihH[2][ks][0], wihH[2][ks][1]);
            mma16816(gxa[0], ah, wihL[0][ks][0], wihL[0][ks][1]);
            mma16816(gxa[1], ah, wihL[1][ks][0], wihL[1][ks][1]);
            mma16816(gxa[2], ah, wihL[2][ks][0], wihL[2][ks][1]);
            mma16816(gxa[0], al, wihH[0][ks][0], wihH[0][ks][1]);
            mma16816(gxa[1], al, wihH[1][ks][0], wihH[1][ks][1]);
            mma16816(gxa[2], al, wihH[2][ks][0], wihH[2][ks][1]);
        }
    }

    for (int t = 0; t < Tn; t += 2) {
        gru_step<0>(t,     sm, sb, x4, xrow, pc, pr, aX, aH, u0, r_l,
                    wihH, wihL, whhH, whhLa, brz_r, brz_z, bn_x, bn_h,
                    hold, gxa, gxb);
        gru_step<1>(t + 1, sm, sb, x4, xrow, pc, pr, aX, aH, u0, r_l,
                    wihH, wihL, whhH, whhLa, brz_r, brz_z, bn_x, bn_h,
                    hold, gxb, gxa);
    }

    // final FC
    float* hf = (float*)(sm + HF);
    #pragma unroll
    for (int i = 0; i < 2; ++i) {
        int row = r_l + 8 * i;
        hf[row * 68 + u0]     = hold[2 * i];
        hf[row * 68 + u0 + 1] = hold[2 * i + 1];
    }
    __syncthreads();
    if (tid < ROWS) {
        float s = fc_b[0];
        #pragma unroll 8
        for (int j = 0; j < Hn; ++j)
            s += hf[tid * 68 + j] * fc_w[j];
        out[r0 + tid] = s;
    }
}

extern "C" void kernel_launch(void* const* d_in, const int* in_sizes, int n_in,
                              void* d_out, int out_size) {
    const float* x    = (const float*)d_in[0];
    const float* w_ih = (const float*)d_in[1];
    const float* w_hh = (const float*)d_in[2];
    const float* b_ih = (const float*)d_in[3];
    const float* b_hh = (const float*)d_in[4];
    const float* fc_w = (const float*)d_in[5];
    const float* fc_b = (const float*)d_in[6];
    float* out = (float*)d_out;

    cudaFuncSetAttribute(gru_fused_tc,
                         cudaFuncAttributeMaxDynamicSharedMemorySize, SMEMB);
    gru_fused_tc<<<Bn / ROWS, NTH, SMEMB>>>(
        x, w_ih, w_hh, b_ih, b_hh, fc_w, fc_b, out);
}

// round 9
// speedup vs baseline: 1.1702x; 1.1702x over previous
#include <cuda_runtime.h>
#include <cuda_bf16.h>
#include <cstdint>

// ============================================================================
// Fully-fused tensor-core GRU, software-pipelined: gx(t+1) MMAs interleave
// with the serial gh(t) chain (dual alternating gh chains).
// B=2048, T=256, F=128, H=64. 128 blocks x 256 threads; 16 rows/block.
// ============================================================================

#define Bn 2048
#define Tn 256
#define Fn 128
#define Hn 64
#define ROWS 16
#define NTH 256

// smem offsets (bytes)
#define WIH_H 0                 // 192 x 272
#define WIH_L 52224
#define WHH_H 104448            // 192 x 144
#define WHH_L 132096
#define XB    159744            // x bf16: hi bufs [2], then lo bufs [2], 4352 each
#define XSZ   4352
#define XLO   8704
#define HBB   177152            // h bf16: hi bufs [2], then lo bufs [2], 2304 each
#define HSZ   2304
#define HLO   4608
#define HF    186368            // fp32 h_last: 16 x 68
#define SMEMB 190720

__device__ __forceinline__ uint32_t smem_u32(const void* p) {
    uint32_t a;
    asm("{ .reg .u64 t; cvta.to.shared.u64 t, %1; cvt.u32.u64 %0, t; }"
        : "=r"(a) : "l"(p));
    return a;
}
__device__ __forceinline__ void ldsm4(uint32_t* r, uint32_t addr) {
    asm volatile("ldmatrix.sync.aligned.m8n8.x4.shared.b16 {%0,%1,%2,%3}, [%4];"
        : "=r"(r[0]), "=r"(r[1]), "=r"(r[2]), "=r"(r[3]) : "r"(addr));
}
__device__ __forceinline__ void ldsm2(uint32_t* r, uint32_t addr) {
    asm volatile("ldmatrix.sync.aligned.m8n8.x2.shared.b16 {%0,%1}, [%2];"
        : "=r"(r[0]), "=r"(r[1]) : "r"(addr));
}
__device__ __forceinline__ void mma16816(float* c, const uint32_t* a,
                                         uint32_t b0, uint32_t b1) {
    asm volatile(
        "mma.sync.aligned.m16n8k16.row.col.f32.bf16.bf16.f32 "
        "{%0,%1,%2,%3}, {%4,%5,%6,%7}, {%8,%9}, {%0,%1,%2,%3};"
        : "+f"(c[0]), "+f"(c[1]), "+f"(c[2]), "+f"(c[3])
        : "r"(a[0]), "r"(a[1]), "r"(a[2]), "r"(a[3]), "r"(b0), "r"(b1));
}
__device__ __forceinline__ void split_store(char* sm, int off_hi, int off_lo,
                                            int boff, float4 v) {
    __nv_bfloat162 h01 = __floats2bfloat162_rn(v.x, v.y);
    __nv_bfloat162 h23 = __floats2bfloat162_rn(v.z, v.w);
    *(uint2*)(sm + off_hi + boff) = make_uint2(*(uint32_t*)&h01, *(uint32_t*)&h23);
    float l0 = v.x - __bfloat162float(__low2bfloat16(h01));
    float l1 = v.y - __bfloat162float(__high2bfloat16(h01));
    float l2 = v.z - __bfloat162float(__low2bfloat16(h23));
    float l3 = v.w - __bfloat162float(__high2bfloat16(h23));
    __nv_bfloat162 s01 = __floats2bfloat162_rn(l0, l1);
    __nv_bfloat162 s23 = __floats2bfloat162_rn(l2, l3);
    *(uint2*)(sm + off_lo + boff) = make_uint2(*(uint32_t*)&s01, *(uint32_t*)&s23);
}
__device__ __forceinline__ float tanh_ap(float v) {
    float r;
    asm("tanh.approx.f32 %0, %1;" : "=f"(r) : "f"(v));
    return r;
}
__device__ __forceinline__ float sig_t(float v) {
    return fmaf(0.5f, tanh_ap(0.5f * v), 0.5f);
}

__global__ void __launch_bounds__(NTH, 1)
gru_fused_tc(const float* __restrict__ x,
             const float* __restrict__ w_ih,
             const float* __restrict__ w_hh,
             const float* __restrict__ b_ih,
             const float* __restrict__ b_hh,
             const float* __restrict__ fc_w,
             const float* __restrict__ fc_b,
             float* __restrict__ out) {
    extern __shared__ char sm[];
    const uint32_t sb = smem_u32(sm);
    const int tid = threadIdx.x;
    const int w   = tid >> 5;
    const int l   = tid & 31;
    const int r0  = blockIdx.x * ROWS;

    // per-lane gate columns & biases
    const int u0 = 8 * w + 2 * (l & 3);
    float brz_r[2], brz_z[2], bn_x[2], bn_h[2];
    #pragma unroll
    for (int j = 0; j < 2; ++j) {
        brz_r[j] = b_ih[u0 + j]      + b_hh[u0 + j];
        brz_z[j] = b_ih[64 + u0 + j] + b_hh[64 + u0 + j];
        bn_x[j]  = b_ih[128 + u0 + j];
        bn_h[j]  = b_hh[128 + u0 + j];
    }

    // weights -> smem hi/lo
    {
        const float4* w4 = (const float4*)w_ih;
        #pragma unroll
        for (int j = 0; j < 24; ++j) {
            int idx = j * 256 + tid;
            int row = idx >> 5, c4 = idx & 31;
            split_store(sm, WIH_H, WIH_L, row * 272 + c4 * 8, w4[idx]);
        }
        const float4* v4 = (const float4*)w_hh;
        #pragma unroll
        for (int j = 0; j < 12; ++j) {
            int idx = j * 256 + tid;
            int row = idx >> 4, c4 = idx & 15;
            split_store(sm, WHH_H, WHH_L, row * 144 + c4 * 8, v4[idx]);
        }
        for (int i = tid; i < (4 * HSZ) / 4; i += NTH)
            *(uint32_t*)(sm + HBB + i * 4) = 0u;
    }
    __syncthreads();

    // resident B fragments (warp w owns n-tiles {w, w+8, w+16})
    const int lq = l & 15;
    uint32_t wihH[3][8][2], wihL[3][8][2], whhH[3][4][2], whhL[3][4][2];
    #pragma unroll
    for (int g = 0; g < 3; ++g) {
        const uint32_t rbase = (uint32_t)(g * 64 + 8 * w + (lq & 7));
        #pragma unroll
        for (int ks = 0; ks < 8; ++ks) {
            uint32_t off = rbase * 272 + ks * 32 + (lq >> 3) * 16;
            ldsm2(wihH[g][ks], sb + WIH_H + off);
            ldsm2(wihL[g][ks], sb + WIH_L + off);
        }
        #pragma unroll
        for (int ks = 0; ks < 4; ++ks) {
            uint32_t off = rbase * 144 + ks * 32 + (lq >> 3) * 16;
            ldsm2(whhH[g][ks], sb + WHH_H + off);
            ldsm2(whhL[g][ks], sb + WHH_L + off);
        }
    }

    // A-fragment lane addresses
    const int mrow  = (l & 7) + ((l >> 3) & 1) * 8;
    const int khalf = (l >> 4) & 1;
    const uint32_t aX = (uint32_t)(mrow * 272 + khalf * 16);
    const uint32_t aH = (uint32_t)(mrow * 144 + khalf * 16);

    // x prefetch mapping: 16 rows x 32 f4 per step, 2 f4/thread
    const int pr = tid >> 4;
    const int pc = (tid & 15) * 2;
    const float4* x4 = (const float4*)x;
    const size_t xrow = (size_t)(r0 + pr) * (Tn * Fn / 4);

    // preload x(0)->buf0, x(1)->buf1
    {
        float4 v0 = x4[xrow + pc];
        float4 v1 = x4[xrow + pc + 1];
        split_store(sm, XB, XB + XLO, pr * 272 + pc * 8, v0);
        split_store(sm, XB, XB + XLO, pr * 272 + (pc + 1) * 8, v1);
        v0 = x4[xrow + 32 + pc];
        v1 = x4[xrow + 32 + pc + 1];
        split_store(sm, XB + XSZ, XB + XLO + XSZ, pr * 272 + pc * 8, v0);
        split_store(sm, XB + XSZ, XB + XLO + XSZ, pr * 272 + (pc + 1) * 8, v1);
    }
    __syncthreads();

    const int r_l = l >> 2;
    float hold[4] = {0.f, 0.f, 0.f, 0.f};

    // ---- prologue: gx(0) from buf0, biases folded ----
    float gxR[4], gxZ[4], gxNx[4];
    #pragma unroll
    for (int i = 0; i < 4; ++i) {
        gxR[i] = brz_r[i & 1]; gxZ[i] = brz_z[i & 1]; gxNx[i] = bn_x[i & 1];
    }
    {
        const uint32_t xh = sb + XB + aX;
        const uint32_t xl = xh + XLO;
        #pragma unroll
        for (int ks = 0; ks < 8; ++ks) {
            uint32_t ah[4], al[4];
            ldsm4(ah, xh + ks * 32);
            ldsm4(al, xl + ks * 32);
            mma16816(gxR,  ah, wihH[0][ks][0], wihH[0][ks][1]);
            mma16816(gxZ,  ah, wihH[1][ks][0], wihH[1][ks][1]);
            mma16816(gxNx, ah, wihH[2][ks][0], wihH[2][ks][1]);
            mma16816(gxR,  ah, wihL[0][ks][0], wihL[0][ks][1]);
            mma16816(gxZ,  ah, wihL[1][ks][0], wihL[1][ks][1]);
            mma16816(gxNx, ah, wihL[2][ks][0], wihL[2][ks][1]);
            mma16816(gxR,  al, wihH[0][ks][0], wihH[0][ks][1]);
            mma16816(gxZ,  al, wihH[1][ks][0], wihH[1][ks][1]);
            mma16816(gxNx, al, wihH[2][ks][0], wihH[2][ks][1]);
        }
    }

    for (int t = 0; t < Tn; ++t) {
        const int cur = t & 1, nxt = cur ^ 1;

        // prefetch x(t+2) from gmem
        float4 p0, p1;
        const bool pf2 = (t + 2 < Tn);
        if (pf2) {
            p0 = x4[xrow + (size_t)(t + 2) * 32 + pc];
            p1 = x4[xrow + (size_t)(t + 2) * 32 + pc + 1];
        }

        // dual gh chains (cc = q&1) and gx(t+1) accumulators, biases folded
        float ghR[2][4], ghZ[2][4], ghN[2][4];
        float gxR2[4], gxZ2[4], gxNx2[4];
        #pragma unroll
        for (int i = 0; i < 4; ++i) {
            ghR[0][i] = 0.f; ghZ[0][i] = 0.f; ghN[0][i] = bn_h[i & 1];
            ghR[1][i] = 0.f; ghZ[1][i] = 0.f; ghN[1][i] = 0.f;
            gxR2[i] = brz_r[i & 1]; gxZ2[i] = brz_z[i & 1]; gxNx2[i] = bn_x[i & 1];
        }

        const uint32_t xh = sb + XB + nxt * XSZ + aX;   // x(t+1)
        const uint32_t xl = xh + XLO;
        const uint32_t hh = sb + HBB + cur * HSZ + aH;  // h(t)
        const uint32_t hl = hh + HLO;

        // interleaved: per q, gh kstep q (chain cc=q&1) + gx ksteps 2q,2q+1
        #pragma unroll
        for (int q = 0; q < 4; ++q) {
            uint32_t hah[4], hal[4];
            ldsm4(hah, hh + q * 32);
            ldsm4(hal, hl + q * 32);
            #pragma unroll
            for (int s = 0; s < 2; ++s) {
                const int ks = 2 * q + s;
                uint32_t ah[4], al[4];
                ldsm4(ah, xh + ks * 32);
                ldsm4(al, xl + ks * 32);
                mma16816(gxR2,  ah, wihH[0][ks][0], wihH[0][ks][1]);
                mma16816(gxZ2,  ah, wihH[1][ks][0], wihH[1][ks][1]);
                mma16816(gxNx2, ah, wihH[2][ks][0], wihH[2][ks][1]);
                mma16816(gxR2,  ah, wihL[0][ks][0], wihL[0][ks][1]);
                mma16816(gxZ2,  ah, wihL[1][ks][0], wihL[1][ks][1]);
                mma16816(gxNx2, ah, wihL[2][ks][0], wihL[2][ks][1]);
                mma16816(gxR2,  al, wihH[0][ks][0], wihH[0][ks][1]);
                mma16816(gxZ2,  al, wihH[1][ks][0], wihH[1][ks][1]);
                mma16816(gxNx2, al, wihH[2][ks][0], wihH[2][ks][1]);
            }
            // x(t+2) smem conversion filler inside the chain region
            if (q == 2 && pf2) {
                split_store(sm, XB + cur * XSZ, XB + XLO + cur * XSZ,
                            pr * 272 + pc * 8, p0);
                split_store(sm, XB + cur * XSZ, XB + XLO + cur * XSZ,
                            pr * 272 + (pc + 1) * 8, p1);
            }
            const int cc = q & 1;
            mma16816(ghR[cc], hah, whhH[0][q][0], whhH[0][q][1]);
            mma16816(ghZ[cc], hah, whhH[1][q][0], whhH[1][q][1]);
            mma16816(ghN[cc], hah, whhH[2][q][0], whhH[2][q][1]);
            mma16816(ghR[cc], hah, whhL[0][q][0], whhL[0][q][1]);
            mma16816(ghZ[cc], hah, whhL[1][q][0], whhL[1][q][1]);
            mma16816(ghN[cc], hah, whhL[2][q][0], whhL[2][q][1]);
            mma16816(ghR[cc], hal, whhH[0][q][0], whhH[0][q][1]);
            mma16816(ghZ[cc], hal, whhH[1][q][0], whhH[1][q][1]);
            mma16816(ghN[cc], hal, whhH[2][q][0], whhH[2][q][1]);
        }

        // gates + h update (merge dual chains here)
        #pragma unroll
        for (int idx = 0; idx < 4; ++idx) {
            float rr = sig_t(ghR[0][idx] + ghR[1][idx] + gxR[idx]);
            float zz = sig_t(ghZ[0][idx] + ghZ[1][idx] + gxZ[idx]);
            float nn = tanh_ap(gxNx[idx] + rr * (ghN[0][idx] + ghN[1][idx]));
            hold[idx] = (1.0f - zz) * nn + zz * hold[idx];
        }

        // store h(t+1) bf16 hi/lo into nxt buffer
        #pragma unroll
        for (int i = 0; i < 2; ++i) {
            int row = r_l + 8 * i;
            float a0 = hold[2 * i], a1 = hold[2 * i + 1];
            __nv_bfloat162 hb2 = __floats2bfloat162_rn(a0, a1);
            *(uint32_t*)(sm + HBB + nxt * HSZ + row * 144 + u0 * 2) =
                *(uint32_t*)&hb2;
            float e0 = a0 - __bfloat162float(__low2bfloat16(hb2));
            float e1 = a1 - __bfloat162float(__high2bfloat16(hb2));
            __nv_bfloat162 lb2 = __floats2bfloat162_rn(e0, e1);
            *(uint32_t*)(sm + HBB + HLO + nxt * HSZ + row * 144 + u0 * 2) =
                *(uint32_t*)&lb2;
        }

        // rotate gx pipeline
        #pragma unroll
        for (int i = 0; i < 4; ++i) {
            gxR[i] = gxR2[i]; gxZ[i] = gxZ2[i]; gxNx[i] = gxNx2[i];
        }

        __syncthreads();
    }

    // final FC
    float* hf = (float*)(sm + HF);
    #pragma unroll
    for (int i = 0; i < 2; ++i) {
        int row = r_l + 8 * i;
        hf[row * 68 + u0]     = hold[2 * i];
        hf[row * 68 + u0 + 1] = hold[2 * i + 1];
    }
    __syncthreads();
    if (tid < ROWS) {
        float s = fc_b[0];
        #pragma unroll 8
        for (int j = 0; j < Hn; ++j)
            s += hf[tid * 68 + j] * fc_w[j];
        out[r0 + tid] = s;
    }
}

extern "C" void kernel_launch(void* const* d_in, const int* in_sizes, int n_in,
                              void* d_out, int out_size) {
    const float* x    = (const float*)d_in[0];
    const float* w_ih = (const float*)d_in[1];
    const float* w_hh = (const float*)d_in[2];
    const float* b_ih = (const float*)d_in[3];
    const float* b_hh = (const float*)d_in[4];
    const float* fc_w = (const float*)d_in[5];
    const float* fc_b = (const float*)d_in[6];
    float* out = (float*)d_out;

    cudaFuncSetAttribute(gru_fused_tc,
                         cudaFuncAttributeMaxDynamicSharedMemorySize, SMEMB);
    gru_fused_tc<<<Bn / ROWS, NTH, SMEMB>>>(
        x, w_ih, w_hh, b_ih, b_hh, fc_w, fc_b, out);
}

// round 10
// speedup vs baseline: 1.2282x; 1.0496x over previous
#include <cuda_runtime.h>
#include <cuda_bf16.h>
#include <cstdint>

// ============================================================================
// Fully-fused tensor-core GRU. gx(t+1) and gh(t) MMA streams interleaved at
// fine grain (pattern gx,gx,gh) so no accumulator recurs within HMMA latency.
// B=2048, T=256, F=128, H=64. 128 blocks x 256 threads; 16 rows/block.
// ============================================================================

#define Bn 2048
#define Tn 256
#define Fn 128
#define Hn 64
#define ROWS 16
#define NTH 256

// smem offsets (bytes)
#define WIH_H 0                 // 192 x 272
#define WIH_L 52224
#define WHH_H 104448            // 192 x 144
#define WHH_L 132096
#define XB    159744            // x bf16: hi bufs [2], then lo bufs [2], 4352 each
#define XSZ   4352
#define XLO   8704
#define HBB   177152            // h bf16: hi bufs [2], then lo bufs [2], 2304 each
#define HSZ   2304
#define HLO   4608
#define HF    186368            // fp32 h_last: 16 x 68
#define SMEMB 190720

__device__ __forceinline__ uint32_t smem_u32(const void* p) {
    uint32_t a;
    asm("{ .reg .u64 t; cvta.to.shared.u64 t, %1; cvt.u32.u64 %0, t; }"
        : "=r"(a) : "l"(p));
    return a;
}
__device__ __forceinline__ void ldsm4(uint32_t* r, uint32_t addr) {
    asm volatile("ldmatrix.sync.aligned.m8n8.x4.shared.b16 {%0,%1,%2,%3}, [%4];"
        : "=r"(r[0]), "=r"(r[1]), "=r"(r[2]), "=r"(r[3]) : "r"(addr));
}
__device__ __forceinline__ void ldsm2(uint32_t* r, uint32_t addr) {
    asm volatile("ldmatrix.sync.aligned.m8n8.x2.shared.b16 {%0,%1}, [%2];"
        : "=r"(r[0]), "=r"(r[1]) : "r"(addr));
}
__device__ __forceinline__ void mma16816(float* c, const uint32_t* a,
                                         uint32_t b0, uint32_t b1) {
    asm volatile(
        "mma.sync.aligned.m16n8k16.row.col.f32.bf16.bf16.f32 "
        "{%0,%1,%2,%3}, {%4,%5,%6,%7}, {%8,%9}, {%0,%1,%2,%3};"
        : "+f"(c[0]), "+f"(c[1]), "+f"(c[2]), "+f"(c[3])
        : "r"(a[0]), "r"(a[1]), "r"(a[2]), "r"(a[3]), "r"(b0), "r"(b1));
}
__device__ __forceinline__ void split_store(char* sm, int off_hi, int off_lo,
                                            int boff, float4 v) {
    __nv_bfloat162 h01 = __floats2bfloat162_rn(v.x, v.y);
    __nv_bfloat162 h23 = __floats2bfloat162_rn(v.z, v.w);
    *(uint2*)(sm + off_hi + boff) = make_uint2(*(uint32_t*)&h01, *(uint32_t*)&h23);
    float l0 = v.x - __bfloat162float(__low2bfloat16(h01));
    float l1 = v.y - __bfloat162float(__high2bfloat16(h01));
    float l2 = v.z - __bfloat162float(__low2bfloat16(h23));
    float l3 = v.w - __bfloat162float(__high2bfloat16(h23));
    __nv_bfloat162 s01 = __floats2bfloat162_rn(l0, l1);
    __nv_bfloat162 s23 = __floats2bfloat162_rn(l2, l3);
    *(uint2*)(sm + off_lo + boff) = make_uint2(*(uint32_t*)&s01, *(uint32_t*)&s23);
}
__device__ __forceinline__ float tanh_ap(float v) {
    float r;
    asm("tanh.approx.f32 %0, %1;" : "=f"(r) : "f"(v));
    return r;
}
__device__ __forceinline__ float sig_t(float v) {
    return fmaf(0.5f, tanh_ap(0.5f * v), 0.5f);
}

__global__ void __launch_bounds__(NTH, 1)
gru_fused_tc(const float* __restrict__ x,
             const float* __restrict__ w_ih,
             const float* __restrict__ w_hh,
             const float* __restrict__ b_ih,
             const float* __restrict__ b_hh,
             const float* __restrict__ fc_w,
             const float* __restrict__ fc_b,
             float* __restrict__ out) {
    extern __shared__ char sm[];
    const uint32_t sb = smem_u32(sm);
    const int tid = threadIdx.x;
    const int w   = tid >> 5;
    const int l   = tid & 31;
    const int r0  = blockIdx.x * ROWS;

    // per-lane gate columns & biases
    const int u0 = 8 * w + 2 * (l & 3);
    float brz_r[2], brz_z[2], bn_x[2], bn_h[2];
    #pragma unroll
    for (int j = 0; j < 2; ++j) {
        brz_r[j] = b_ih[u0 + j]      + b_hh[u0 + j];
        brz_z[j] = b_ih[64 + u0 + j] + b_hh[64 + u0 + j];
        bn_x[j]  = b_ih[128 + u0 + j];
        bn_h[j]  = b_hh[128 + u0 + j];
    }

    // weights -> smem hi/lo
    {
        const float4* w4 = (const float4*)w_ih;
        #pragma unroll
        for (int j = 0; j < 24; ++j) {
            int idx = j * 256 + tid;
            int row = idx >> 5, c4 = idx & 31;
            split_store(sm, WIH_H, WIH_L, row * 272 + c4 * 8, w4[idx]);
        }
        const float4* v4 = (const float4*)w_hh;
        #pragma unroll
        for (int j = 0; j < 12; ++j) {
            int idx = j * 256 + tid;
            int row = idx >> 4, c4 = idx & 15;
            split_store(sm, WHH_H, WHH_L, row * 144 + c4 * 8, v4[idx]);
        }
        for (int i = tid; i < (4 * HSZ) / 4; i += NTH)
            *(uint32_t*)(sm + HBB + i * 4) = 0u;
    }
    __syncthreads();

    // resident B fragments (warp w owns n-tiles {w, w+8, w+16})
    const int lq = l & 15;
    uint32_t wihH[3][8][2], wihL[3][8][2], whhH[3][4][2], whhL[3][4][2];
    #pragma unroll
    for (int g = 0; g < 3; ++g) {
        const uint32_t rbase = (uint32_t)(g * 64 + 8 * w + (lq & 7));
        #pragma unroll
        for (int ks = 0; ks < 8; ++ks) {
            uint32_t off = rbase * 272 + ks * 32 + (lq >> 3) * 16;
            ldsm2(wihH[g][ks], sb + WIH_H + off);
            ldsm2(wihL[g][ks], sb + WIH_L + off);
        }
        #pragma unroll
        for (int ks = 0; ks < 4; ++ks) {
            uint32_t off = rbase * 144 + ks * 32 + (lq >> 3) * 16;
            ldsm2(whhH[g][ks], sb + WHH_H + off);
            ldsm2(whhL[g][ks], sb + WHH_L + off);
        }
    }

    // A-fragment lane addresses
    const int mrow  = (l & 7) + ((l >> 3) & 1) * 8;
    const int khalf = (l >> 4) & 1;
    const uint32_t aX = (uint32_t)(mrow * 272 + khalf * 16);
    const uint32_t aH = (uint32_t)(mrow * 144 + khalf * 16);

    // x prefetch mapping: 16 rows x 32 f4 per step, 2 f4/thread
    const int pr = tid >> 4;
    const int pc = (tid & 15) * 2;
    const float4* x4 = (const float4*)x;
    const size_t xrow = (size_t)(r0 + pr) * (Tn * Fn / 4);

    // preload x(0)->buf0, x(1)->buf1
    {
        float4 v0 = x4[xrow + pc];
        float4 v1 = x4[xrow + pc + 1];
        split_store(sm, XB, XB + XLO, pr * 272 + pc * 8, v0);
        split_store(sm, XB, XB + XLO, pr * 272 + (pc + 1) * 8, v1);
        v0 = x4[xrow + 32 + pc];
        v1 = x4[xrow + 32 + pc + 1];
        split_store(sm, XB + XSZ, XB + XLO + XSZ, pr * 272 + pc * 8, v0);
        split_store(sm, XB + XSZ, XB + XLO + XSZ, pr * 272 + (pc + 1) * 8, v1);
    }
    __syncthreads();

    const int r_l = l >> 2;
    float hold[4] = {0.f, 0.f, 0.f, 0.f};

    // ---- prologue: gx(0) from buf0, biases folded ----
    float gxR[4], gxZ[4], gxNx[4];
    #pragma unroll
    for (int i = 0; i < 4; ++i) {
        gxR[i] = brz_r[i & 1]; gxZ[i] = brz_z[i & 1]; gxNx[i] = bn_x[i & 1];
    }
    {
        const uint32_t xh = sb + XB + aX;
        const uint32_t xl = xh + XLO;
        #pragma unroll
        for (int ks = 0; ks < 8; ++ks) {
            uint32_t ah[4], al[4];
            ldsm4(ah, xh + ks * 32);
            ldsm4(al, xl + ks * 32);
            mma16816(gxR,  ah, wihH[0][ks][0], wihH[0][ks][1]);
            mma16816(gxZ,  ah, wihH[1][ks][0], wihH[1][ks][1]);
            mma16816(gxNx, ah, wihH[2][ks][0], wihH[2][ks][1]);
            mma16816(gxR,  ah, wihL[0][ks][0], wihL[0][ks][1]);
            mma16816(gxZ,  ah, wihL[1][ks][0], wihL[1][ks][1]);
            mma16816(gxNx, ah, wihL[2][ks][0], wihL[2][ks][1]);
            mma16816(gxR,  al, wihH[0][ks][0], wihH[0][ks][1]);
            mma16816(gxZ,  al, wihH[1][ks][0], wihH[1][ks][1]);
            mma16816(gxNx, al, wihH[2][ks][0], wihH[2][ks][1]);
        }
    }

    for (int t = 0; t < Tn; ++t) {
        const int cur = t & 1, nxt = cur ^ 1;

        // prefetch x(t+2) from gmem
        float4 p0, p1;
        const bool pf2 = (t + 2 < Tn);
        if (pf2) {
            p0 = x4[xrow + (size_t)(t + 2) * 32 + pc];
            p1 = x4[xrow + (size_t)(t + 2) * 32 + pc + 1];
        }

        // gh accumulators (bn_h folded into ghN) and gx(t+1) accumulators
        float ghR[4], ghZ[4], ghN[4];
        float gxR2[4], gxZ2[4], gxNx2[4];
        #pragma unroll
        for (int i = 0; i < 4; ++i) {
            ghR[i] = 0.f; ghZ[i] = 0.f; ghN[i] = bn_h[i & 1];
            gxR2[i] = brz_r[i & 1]; gxZ2[i] = brz_z[i & 1]; gxNx2[i] = bn_x[i & 1];
        }

        const uint32_t xh = sb + XB + nxt * XSZ + aX;   // x(t+1)
        const uint32_t xl = xh + XLO;
        const uint32_t hh = sb + HBB + cur * HSZ + aH;  // h(t)
        const uint32_t hl = hh + HLO;

        // Fine-grained interleave: per q (gh kstep), two gx ksteps; pattern
        // gx,gx,gh with gate rotation -> same accumulator recurs every 4-5
        // (gx) or ~9 (gh) MMA slots, above HMMA accumulate latency.
        #pragma unroll
        for (int q = 0; q < 4; ++q) {
            uint32_t hah[4], hal[4];
            ldsm4(hah, hh + q * 32);

            // ---- s = 0: gx kstep 2q (9 MMAs) + gh hah x whhH/whhL (5 MMAs)
            {
                const int ks = 2 * q;
                uint32_t ah[4], al[4];
                ldsm4(ah, xh + ks * 32);
                ldsm4(al, xl + ks * 32);
                mma16816(gxR2,  ah, wihH[0][ks][0], wihH[0][ks][1]);
                mma16816(gxZ2,  ah, wihH[1][ks][0], wihH[1][ks][1]);
                mma16816(ghR,   hah, whhH[0][q][0], whhH[0][q][1]);
                mma16816(gxNx2, ah, wihH[2][ks][0], wihH[2][ks][1]);
                mma16816(gxR2,  ah, wihL[0][ks][0], wihL[0][ks][1]);
                mma16816(ghZ,   hah, whhH[1][q][0], whhH[1][q][1]);
                mma16816(gxZ2,  ah, wihL[1][ks][0], wihL[1][ks][1]);
                mma16816(gxNx2, ah, wihL[2][ks][0], wihL[2][ks][1]);
                mma16816(ghN,   hah, whhH[2][q][0], whhH[2][q][1]);
                mma16816(gxR2,  al, wihH[0][ks][0], wihH[0][ks][1]);
                mma16816(gxZ2,  al, wihH[1][ks][0], wihH[1][ks][1]);
                mma16816(ghR,   hah, whhL[0][q][0], whhL[0][q][1]);
                mma16816(gxNx2, al, wihH[2][ks][0], wihH[2][ks][1]);
                mma16816(ghZ,   hah, whhL[1][q][0], whhL[1][q][1]);
            }
            // ---- s = 1: gx kstep 2q+1 (9 MMAs) + gh remainder (4 MMAs)
            {
                const int ks = 2 * q + 1;
                uint32_t ah[4], al[4];
                ldsm4(ah, xh + ks * 32);
                ldsm4(al, xl + ks * 32);
                ldsm4(hal, hl + q * 32);
                mma16816(gxR2,  ah, wihH[0][ks][0], wihH[0][ks][1]);
                mma16816(gxZ2,  ah, wihH[1][ks][0], wihH[1][ks][1]);
                mma16816(ghN,   hah, whhL[2][q][0], whhL[2][q][1]);
                mma16816(gxNx2, ah, wihH[2][ks][0], wihH[2][ks][1]);
                mma16816(gxR2,  ah, wihL[0][ks][0], wihL[0][ks][1]);
                mma16816(ghR,   hal, whhH[0][q][0], whhH[0][q][1]);
                mma16816(gxZ2,  ah, wihL[1][ks][0], wihL[1][ks][1]);
                mma16816(gxNx2, ah, wihL[2][ks][0], wihL[2][ks][1]);
                mma16816(ghZ,   hal, whhH[1][q][0], whhH[1][q][1]);
                mma16816(gxR2,  al, wihH[0][ks][0], wihH[0][ks][1]);
                mma16816(gxZ2,  al, wihH[1][ks][0], wihH[1][ks][1]);
                mma16816(ghN,   hal, whhH[2][q][0], whhH[2][q][1]);
                mma16816(gxNx2, al, wihH[2][ks][0], wihH[2][ks][1]);
            }
        }

        // gates + h update
        #pragma unroll
        for (int idx = 0; idx < 4; ++idx) {
            float rr = sig_t(ghR[idx] + gxR[idx]);
            float zz = sig_t(ghZ[idx] + gxZ[idx]);
            float nn = tanh_ap(gxNx[idx] + rr * ghN[idx]);
            hold[idx] = (1.0f - zz) * nn + zz * hold[idx];
        }

        // store x(t+2) into buffer parity cur (x(t) is dead)
        if (pf2) {
            split_store(sm, XB + cur * XSZ, XB + XLO + cur * XSZ,
                        pr * 272 + pc * 8, p0);
            split_store(sm, XB + cur * XSZ, XB + XLO + cur * XSZ,
                        pr * 272 + (pc + 1) * 8, p1);
        }

        // store h(t+1) bf16 hi/lo into nxt buffer
        #pragma unroll
        for (int i = 0; i < 2; ++i) {
            int row = r_l + 8 * i;
            float a0 = hold[2 * i], a1 = hold[2 * i + 1];
            __nv_bfloat162 hb2 = __floats2bfloat162_rn(a0, a1);
            *(uint32_t*)(sm + HBB + nxt * HSZ + row * 144 + u0 * 2) =
                *(uint32_t*)&hb2;
            float e0 = a0 - __bfloat162float(__low2bfloat16(hb2));
            float e1 = a1 - __bfloat162float(__high2bfloat16(hb2));
            __nv_bfloat162 lb2 = __floats2bfloat162_rn(e0, e1);
            *(uint32_t*)(sm + HBB + HLO + nxt * HSZ + row * 144 + u0 * 2) =
                *(uint32_t*)&lb2;
        }

        // rotate gx pipeline
        #pragma unroll
        for (int i = 0; i < 4; ++i) {
            gxR[i] = gxR2[i]; gxZ[i] = gxZ2[i]; gxNx[i] = gxNx2[i];
        }

        __syncthreads();
    }

    // final FC
    float* hf = (float*)(sm + HF);
    #pragma unroll
    for (int i = 0; i < 2; ++i) {
        int row = r_l + 8 * i;
        hf[row * 68 + u0]     = hold[2 * i];
        hf[row * 68 + u0 + 1] = hold[2 * i + 1];
    }
    __syncthreads();
    if (tid < ROWS) {
        float s = fc_b[0];
        #pragma unroll 8
        for (int j = 0; j < Hn; ++j)
            s += hf[tid * 68 + j] * fc_w[j];
        out[r0 + tid] = s;
    }
}

extern "C" void kernel_launch(void* const* d_in, const int* in_sizes, int n_in,
                              void* d_out, int out_size) {
    const float* x    = (const float*)d_in[0];
    const float* w_ih = (const float*)d_in[1];
    const float* w_hh = (const float*)d_in[2];
    const float* b_ih = (const float*)d_in[3];
    const float* b_hh = (const float*)d_in[4];
    const float* fc_w = (const float*)d_in[5];
    const float* fc_b = (const float*)d_in[6];
    float* out = (float*)d_out;

    cudaFuncSetAttribute(gru_fused_tc,
                         cudaFuncAttributeMaxDynamicSharedMemorySize, SMEMB);
    gru_fused_tc<<<Bn / ROWS, NTH, SMEMB>>>(
        x, w_ih, w_hh, b_ih, b_hh, fc_w, fc_b, out);
}